// round 3
// baseline (speedup 1.0000x reference)
#include <cuda_runtime.h>
#include <math.h>
#include <stdint.h>

// Problem constants
#define BB 64
#define NN 4096
#define FF 128
#define KK 64
#define TN 128            // rows (nodes) per EM tile
#define NTILES (NN / TN)  // 32
#define NPART 16          // partial-sum slots (CTAs per batch in em_kernel)
#define TPC (NTILES / NPART) // tiles per CTA = 2
#define XP 132            // xs smem pitch (floats), mult of 4 for float4
#define MP 68             // muT smem pitch
#define PP 68             // P smem pitch

// Scratch (allocation-free rule: __device__ globals)
__device__ float g_mean[BB][FF];
__device__ float g_inv[BB][FF];
__device__ float g_muA[BB][KK][FF];
__device__ float g_muB[BB][KK][FF];
__device__ float g_part[BB * NPART * KK * FF];   // 33.5 MB partials

// ---------------------------------------------------------------------------
// Kernel 1: masked per-(b,f) mean and inv-std over N nodes.
// grid: B blocks, 512 threads. t&31 -> float4 feature group, t>>5 -> row group.
// ---------------------------------------------------------------------------
__global__ void __launch_bounds__(512)
stats_kernel(const float* __restrict__ emb, const int* __restrict__ nbn) {
    int b = blockIdx.x;
    int t = threadIdx.x;
    int fg = t & 31;
    int rg = t >> 5;        // 0..15
    int nb = nbn[b];
    const float4* e = (const float4*)(emb + (size_t)b * NN * FF);
    float4 s  = make_float4(0.f, 0.f, 0.f, 0.f);
    float4 s2 = make_float4(0.f, 0.f, 0.f, 0.f);
    for (int r = rg; r < nb; r += 16) {
        float4 v = e[(size_t)r * 32 + fg];
        s.x += v.x; s.y += v.y; s.z += v.z; s.w += v.w;
        s2.x += v.x * v.x; s2.y += v.y * v.y; s2.z += v.z * v.z; s2.w += v.w * v.w;
    }
    __shared__ float sh[16][128 + 4];
    __shared__ float sh2[16][128 + 4];
    sh[rg][fg * 4 + 0] = s.x;  sh[rg][fg * 4 + 1] = s.y;
    sh[rg][fg * 4 + 2] = s.z;  sh[rg][fg * 4 + 3] = s.w;
    sh2[rg][fg * 4 + 0] = s2.x; sh2[rg][fg * 4 + 1] = s2.y;
    sh2[rg][fg * 4 + 2] = s2.z; sh2[rg][fg * 4 + 3] = s2.w;
    __syncthreads();
    if (t < 128) {
        float ss = 0.f, ss2 = 0.f;
        #pragma unroll
        for (int g = 0; g < 16; g++) { ss += sh[g][t]; ss2 += sh2[g][t]; }
        float n = (float)nb;
        float mean = ss / n;
        float var = ss2 / n - mean * mean;
        g_mean[b][t] = mean;
        g_inv[b][t] = rsqrtf(var + 1e-5f);
    }
}

// ---------------------------------------------------------------------------
// Kernel 2: mu init from x[:, init_idx] (normalized on the fly)
// ---------------------------------------------------------------------------
__global__ void __launch_bounds__(256)
init_mu_kernel(const float* __restrict__ emb, const int* __restrict__ nbn,
               const int* __restrict__ init_idx) {
    int b = blockIdx.x;
    int nb = nbn[b];
    for (int i = threadIdx.x; i < KK * FF; i += blockDim.x) {
        int k = i >> 7;
        int f = i & 127;
        int r = init_idx[k];
        float v = 0.f;
        if (r >= 0 && r < nb) {
            v = (emb[((size_t)b * NN + r) * FF + f] - g_mean[b][f]) * g_inv[b][f];
        }
        g_muA[b][k][f] = v;
    }
}

// ---------------------------------------------------------------------------
// Kernel 3: fused E+M step with persistent M accumulators.
// grid: (NPART, B), 256 threads, ~138 KB smem, 1 CTA/SM.
// Each CTA processes TPC=2 n-tiles, accumulating its M partial in registers,
// then writes plain STG.128 partials (no atomics).
// ---------------------------------------------------------------------------
__global__ void __launch_bounds__(256, 1)
em_kernel(const float* __restrict__ emb, const int* __restrict__ nbn,
          const float* __restrict__ mu_in) {
    int b = blockIdx.y;
    int part = blockIdx.x;
    int t = threadIdx.x;
    int nb = nbn[b];

    extern __shared__ float sm[];
    float* xs  = sm;                    // [TN][XP]
    float* msT = xs + TN * XP;          // [FF][MP]  mu transposed: msT[f][k]
    float* Pt  = msT + FF * MP;         // [TN][PP]  likelihood
    float* x2  = Pt + TN * PP;          // [TN]
    float* m2  = x2 + TN;               // [KK]
    float* rin = m2 + KK;               // [TN]

    int fl = t & 127;
    float meanf = g_mean[b][fl];
    float invf  = g_inv[b][fl];

    // ---- load mu transposed (once per CTA) ----
    const float* mu = mu_in + (size_t)b * KK * FF;
    #pragma unroll
    for (int j = 0; j < (KK * FF) / 256; j++) {
        int idx = t + 256 * j;
        int k = idx >> 7;
        int f = idx & 127;
        msT[f * MP + k] = mu[idx];
    }
    __syncthreads();
    // ---- m2 per cluster (once) ----
    if (t < KK) {
        float s = 0.f;
        #pragma unroll 8
        for (int f = 0; f < FF; f++) { float v = msT[f * MP + t]; s += v * v; }
        m2[t] = s;
    }

    // E-step thread mapping
    int tk4 = t & 15;   // k block of 4
    int tn8 = t >> 4;   // n block of 8
    int k0 = tk4 * 4;
    int nr0 = tn8 * 8;
    // M-step thread mapping
    int tf = t & 31;    // f block of 4
    int tk8 = t >> 5;   // k block of 8
    int f0 = tf * 4;
    int kk0 = tk8 * 8;

    // persistent M accumulators
    float4 c2[8];
    #pragma unroll
    for (int i = 0; i < 8; i++) c2[i] = make_float4(0.f, 0.f, 0.f, 0.f);

    for (int tile = part * TPC; tile < part * TPC + TPC; tile++) {
        int n0 = tile * TN;
        // ---- load x tile ----
        const float* e = emb + ((size_t)b * NN + n0) * FF;
        #pragma unroll
        for (int j = 0; j < (TN * FF) / 256; j++) {
            int idx = t + 256 * j;
            int r = idx >> 7;
            float v = e[(size_t)r * FF + fl];
            float xv = ((n0 + r) < nb) ? (v - meanf) * invf : 0.f;
            xs[r * XP + fl] = xv;
        }
        __syncthreads();

        // ---- x2 per row ----
        if (t < TN) {
            float s = 0.f;
            #pragma unroll 8
            for (int f = 0; f < FF; f++) { float v = xs[t * XP + f]; s += v * v; }
            x2[t] = s;
        }
        __syncthreads();

        // ---- E-step GEMM: S[n][k] = sum_f x[n][f] * mu[k][f] ----
        float acc[8][4];
        #pragma unroll
        for (int i = 0; i < 8; i++)
            #pragma unroll
            for (int j = 0; j < 4; j++) acc[i][j] = 0.f;

        for (int f = 0; f < FF; f += 4) {
            float4 xv[8];
            #pragma unroll
            for (int i = 0; i < 8; i++)
                xv[i] = *(const float4*)&xs[(nr0 + i) * XP + f];
            #pragma unroll
            for (int j = 0; j < 4; j++) {
                float4 m4 = *(const float4*)&msT[(f + j) * MP + k0];
                #pragma unroll
                for (int i = 0; i < 8; i++) {
                    float xf = (j == 0) ? xv[i].x : (j == 1) ? xv[i].y
                             : (j == 2) ? xv[i].z : xv[i].w;
                    acc[i][0] += xf * m4.x;
                    acc[i][1] += xf * m4.y;
                    acc[i][2] += xf * m4.z;
                    acc[i][3] += xf * m4.w;
                }
            }
        }

        // ---- likelihood = exp(-0.5*(x2 - 2 x.mu + m2)) + 1e-20 ----
        #pragma unroll
        for (int i = 0; i < 8; i++) {
            float xx = x2[nr0 + i];
            #pragma unroll
            for (int j = 0; j < 4; j++) {
                float nrm = xx - 2.f * acc[i][j] + m2[k0 + j];
                Pt[(nr0 + i) * PP + k0 + j] = __expf(-0.5f * nrm) + 1e-20f;
            }
        }
        __syncthreads();

        // ---- row sums -> inverse ----
        if (t < TN) {
            float s = 0.f;
            #pragma unroll 8
            for (int k = 0; k < KK; k++) s += Pt[t * PP + k];
            rin[t] = 1.f / (s + 1e-40f);
        }
        __syncthreads();

        // ---- fold row inverse into x tile ----
        #pragma unroll
        for (int j = 0; j < (TN * FF) / 256; j++) {
            int idx = t + 256 * j;
            int r = idx >> 7;
            xs[r * XP + fl] *= rin[r];
        }
        __syncthreads();

        // ---- M-step GEMM accumulate: c2[k][f] += sum_n lik[n][k]*xsc[n][f] ----
        for (int n = 0; n < TN; n++) {
            float4 xv = *(const float4*)&xs[n * XP + f0];
            float4 p0 = *(const float4*)&Pt[n * PP + kk0];
            float4 p1 = *(const float4*)&Pt[n * PP + kk0 + 4];
            float pk[8] = {p0.x, p0.y, p0.z, p0.w, p1.x, p1.y, p1.z, p1.w};
            #pragma unroll
            for (int i = 0; i < 8; i++) {
                c2[i].x += pk[i] * xv.x;
                c2[i].y += pk[i] * xv.y;
                c2[i].z += pk[i] * xv.z;
                c2[i].w += pk[i] * xv.w;
            }
        }
        __syncthreads();   // xs/Pt reused next tile
    }

    // ---- write partials (plain stores, no atomics) ----
    float* mp = g_part + ((size_t)(b * NPART + part)) * KK * FF;
    #pragma unroll
    for (int i = 0; i < 8; i++) {
        *(float4*)&mp[(kk0 + i) * FF + f0] = c2[i];
    }
}

// ---------------------------------------------------------------------------
// Kernel 4: reduce partials -> mu_out.  grid: B blocks, 256 threads.
// ---------------------------------------------------------------------------
__global__ void __launch_bounds__(256)
reduce_mu_kernel(float* __restrict__ mu_out) {
    int b = blockIdx.x;
    const float4* p = (const float4*)(g_part + (size_t)b * NPART * KK * FF);
    float4* o = (float4*)(mu_out + (size_t)b * KK * FF);
    for (int i = threadIdx.x; i < (KK * FF) / 4; i += 256) {
        float4 a = make_float4(0.f, 0.f, 0.f, 0.f);
        #pragma unroll
        for (int pp = 0; pp < NPART; pp++) {
            float4 v = p[pp * ((KK * FF) / 4) + i];
            a.x += v.x; a.y += v.y; a.z += v.z; a.w += v.w;
        }
        o[i] = a;
    }
}

// ---------------------------------------------------------------------------
// Kernel 5: out[b] = sigmoid( mean_k(mu[b,k,:] . w) + bias )
// ---------------------------------------------------------------------------
__global__ void __launch_bounds__(128)
final_kernel(const float* __restrict__ mu, const float* __restrict__ w,
             const float* __restrict__ bias, float* __restrict__ out) {
    int b = blockIdx.x;
    int t = threadIdx.x;
    const float* m = mu + (size_t)b * KK * FF;
    float s = 0.f;
    for (int k = 0; k < KK; k++) s += m[k * FF + t];
    float v = s * w[t] * (1.f / (float)KK);
    __shared__ float sh[128];
    sh[t] = v;
    __syncthreads();
    for (int off = 64; off > 0; off >>= 1) {
        if (t < off) sh[t] += sh[t + off];
        __syncthreads();
    }
    if (t == 0) {
        float logit = sh[0] + bias[0];
        out[b] = 1.f / (1.f + expf(-logit));
    }
}

// ---------------------------------------------------------------------------
// Launch
// ---------------------------------------------------------------------------
extern "C" void kernel_launch(void* const* d_in, const int* in_sizes, int n_in,
                              void* d_out, int out_size) {
    const float* emb   = (const float*)d_in[0];  // [B,N,F]
    // d_in[1] = mask (implied by batch_nb_nodes; not needed)
    const float* fc_w  = (const float*)d_in[2];  // [1,F]
    const float* fc_b  = (const float*)d_in[3];  // [1]
    const int*   nbn   = (const int*)d_in[4];    // [B]
    const int*   iidx  = (const int*)d_in[5];    // [K]
    float* out = (float*)d_out;                  // [B]

    (void)in_sizes; (void)n_in; (void)out_size;

    float* muA; cudaGetSymbolAddress((void**)&muA, g_muA);
    float* muB; cudaGetSymbolAddress((void**)&muB, g_muB);

    const int EM_SMEM = (TN * XP + FF * MP + TN * PP + TN + KK + TN) * (int)sizeof(float);
    cudaFuncSetAttribute(em_kernel, cudaFuncAttributeMaxDynamicSharedMemorySize, EM_SMEM);

    dim3 em_grid(NPART, BB);

    stats_kernel<<<BB, 512>>>(emb, nbn);
    init_mu_kernel<<<BB, 256>>>(emb, nbn, iidx);          // muA = init

    em_kernel<<<em_grid, 256, EM_SMEM>>>(emb, nbn, muA);  // step 1
    reduce_mu_kernel<<<BB, 256>>>(muB);
    em_kernel<<<em_grid, 256, EM_SMEM>>>(emb, nbn, muB);  // step 2
    reduce_mu_kernel<<<BB, 256>>>(muA);
    em_kernel<<<em_grid, 256, EM_SMEM>>>(emb, nbn, muA);  // step 3
    reduce_mu_kernel<<<BB, 256>>>(muB);
    em_kernel<<<em_grid, 256, EM_SMEM>>>(emb, nbn, muB);  // step 4
    reduce_mu_kernel<<<BB, 256>>>(muA);

    final_kernel<<<BB, 128>>>(muA, fc_w, fc_b, out);
}

// round 13
// speedup vs baseline: 1.2735x; 1.2735x over previous
#include <cuda_runtime.h>
#include <cuda_bf16.h>
#include <math.h>
#include <stdint.h>

// Problem constants
#define BB 64
#define NN 4096
#define FF 128
#define KK 64
#define TN 128              // rows (nodes) per EM tile
#define NTILES 32
#define NPART 4             // partial-sum slots (CTAs per batch)
#define TPC 8               // tiles per CTA

#define PITCH 264           // bytes per bf16 row (132 bf16: 128 data + 4 pad)

// smem byte offsets (single extern char array)
#define OFF_XH  0           // x hi, n-major [128][132] bf16
#define OFF_XL  33792       // x lo
#define OFF_XTH 67584       // x hi, f-major [128][132] bf16 (cols = n)
#define OFF_XTL 101376
#define OFF_MUH 135168      // mu hi [64][132] bf16 (k rows, f contiguous)
#define OFF_MUL 152064
#define OFF_PTH 168960      // P^T hi [64][132] bf16 (k rows, n contiguous)
#define OFF_PTL 185856
#define OFF_X2  202752      // float[128]
#define OFF_M2  203264      // float[64]
#define OFF_RS  203520      // float[128] row sums
#define SMEM_TOTAL 204032

// Scratch (__device__ globals; no allocs allowed)
__device__ float g_mean[BB][FF];
__device__ float g_inv[BB][FF];
__device__ float g_muA[BB][KK][FF];   // [k][f]
__device__ float g_muB[BB][KK][FF];
__device__ float g_part[BB * NPART * KK * FF];   // 8 MB partials

// ---------------------------------------------------------------------------
// helpers
// ---------------------------------------------------------------------------
__device__ __forceinline__ uint32_t bpack(__nv_bfloat16 lo, __nv_bfloat16 hi) {
    return (uint32_t)__bfloat16_as_ushort(lo) | ((uint32_t)__bfloat16_as_ushort(hi) << 16);
}

// mma.sync m16n8k16 bf16 x bf16 -> f32 (arch-agnostic PTX, works on sm_103)
__device__ __forceinline__ void mma16816(float* d, const uint32_t* a, const uint32_t* bfr) {
    asm volatile(
        "mma.sync.aligned.m16n8k16.row.col.f32.bf16.bf16.f32 "
        "{%0,%1,%2,%3}, {%4,%5,%6,%7}, {%8,%9}, {%0,%1,%2,%3};\n"
        : "+f"(d[0]), "+f"(d[1]), "+f"(d[2]), "+f"(d[3])
        : "r"(a[0]), "r"(a[1]), "r"(a[2]), "r"(a[3]), "r"(bfr[0]), "r"(bfr[1]));
}

// fast 2^y via round + degree-5 poly + exponent-bit scale (no MUFU).
// Clamped so y <= -126 -> ~0 (matches fp32 exp underflow; +1e-20 added by caller).
__device__ __forceinline__ float fexp2(float y) {
    y = fmaxf(y, -126.0f);
    int n = __float2int_rn(y);
    float f = y - (float)n;
    float p = 1.3333558e-3f;
    p = fmaf(p, f, 9.6181291e-3f);
    p = fmaf(p, f, 5.5504109e-2f);
    p = fmaf(p, f, 2.4022651e-1f);
    p = fmaf(p, f, 6.9314718e-1f);
    p = fmaf(p, f, 1.0f);
    return p * __int_as_float((n + 127) << 23);
}

// ---------------------------------------------------------------------------
// Kernel 0: no-op to align ncu "-s 5 -c 1" so launch #6 = em_kernel
// ---------------------------------------------------------------------------
__global__ void noop_kernel() {}

// ---------------------------------------------------------------------------
// Kernel 1: masked per-(b,f) mean and inv-std
// ---------------------------------------------------------------------------
__global__ void __launch_bounds__(512)
stats_kernel(const float* __restrict__ emb, const int* __restrict__ nbn) {
    int b = blockIdx.x;
    int t = threadIdx.x;
    int fg = t & 31;
    int rg = t >> 5;
    int nb = nbn[b];
    const float4* e = (const float4*)(emb + (size_t)b * NN * FF);
    float4 s  = make_float4(0.f, 0.f, 0.f, 0.f);
    float4 s2 = make_float4(0.f, 0.f, 0.f, 0.f);
    for (int r = rg; r < nb; r += 16) {
        float4 v = e[(size_t)r * 32 + fg];
        s.x += v.x; s.y += v.y; s.z += v.z; s.w += v.w;
        s2.x += v.x * v.x; s2.y += v.y * v.y; s2.z += v.z * v.z; s2.w += v.w * v.w;
    }
    __shared__ float sh[16][132];
    __shared__ float sh2[16][132];
    sh[rg][fg * 4 + 0] = s.x;  sh[rg][fg * 4 + 1] = s.y;
    sh[rg][fg * 4 + 2] = s.z;  sh[rg][fg * 4 + 3] = s.w;
    sh2[rg][fg * 4 + 0] = s2.x; sh2[rg][fg * 4 + 1] = s2.y;
    sh2[rg][fg * 4 + 2] = s2.z; sh2[rg][fg * 4 + 3] = s2.w;
    __syncthreads();
    if (t < 128) {
        float ss = 0.f, ss2 = 0.f;
        #pragma unroll
        for (int g = 0; g < 16; g++) { ss += sh[g][t]; ss2 += sh2[g][t]; }
        float n = (float)nb;
        float mean = ss / n;
        float var = ss2 / n - mean * mean;
        g_mean[b][t] = mean;
        g_inv[b][t] = rsqrtf(var + 1e-5f);
    }
}

// ---------------------------------------------------------------------------
// Kernel 2: mu init ([k][f] layout)
// ---------------------------------------------------------------------------
__global__ void __launch_bounds__(256)
init_mu_kernel(const float* __restrict__ emb, const int* __restrict__ nbn,
               const int* __restrict__ init_idx) {
    int b = blockIdx.x;
    int nb = nbn[b];
    for (int i = threadIdx.x; i < KK * FF; i += blockDim.x) {
        int k = i >> 7;
        int f = i & 127;
        int r = init_idx[k];
        float v = 0.f;
        if (r >= 0 && r < nb) {
            v = (emb[((size_t)b * NN + r) * FF + f] - g_mean[b][f]) * g_inv[b][f];
        }
        g_muA[b][k][f] = v;
    }
}

// ---------------------------------------------------------------------------
// Kernel 3: fused E+M step via mma.sync (split-bf16, 3 terms per GEMM).
// grid: (NPART, B), 256 threads (8 warps), ~204 KB smem, 1 CTA/SM.
// ---------------------------------------------------------------------------
__global__ void __launch_bounds__(256, 1)
em_kernel(const float* __restrict__ emb, const int* __restrict__ nbn,
          const float* __restrict__ mu_in) {
    extern __shared__ char sm[];
    float* x2s = (float*)(sm + OFF_X2);
    float* m2s = (float*)(sm + OFF_M2);
    float* rs  = (float*)(sm + OFF_RS);

    int b = blockIdx.y;
    int part = blockIdx.x;
    int t = threadIdx.x;
    int w = t >> 5;
    int ln = t & 31;
    int g = ln >> 2;
    int tg = ln & 3;
    int nb = nbn[b];

    // ---- phase 0 (once per CTA): mu -> MUH/MUL bf16, m2 ----
    const float* mu = mu_in + (size_t)b * KK * FF;
    for (int i = t; i < KK * FF; i += 256) {
        int k = i >> 7, f = i & 127;
        float v = mu[i];
        __nv_bfloat16 h = __float2bfloat16(v);
        __nv_bfloat16 l = __float2bfloat16(v - __bfloat162float(h));
        *(__nv_bfloat16*)(sm + OFF_MUH + k * PITCH + f * 2) = h;
        *(__nv_bfloat16*)(sm + OFF_MUL + k * PITCH + f * 2) = l;
    }
    if (t < KK) {
        const float4* m4 = (const float4*)(mu + (size_t)t * FF);
        float s = 0.f;
        #pragma unroll 8
        for (int q = 0; q < FF / 4; q++) {
            float4 u = m4[q];
            s += u.x * u.x + u.y * u.y + u.z * u.z + u.w * u.w;
        }
        m2s[t] = s;
    }

    // preloaded per-thread stats for phase 1 (f lanes fixed = 4*ln..4*ln+3)
    float4 mean4 = *(const float4*)(&g_mean[b][ln * 4]);
    float4 inv4  = *(const float4*)(&g_inv[b][ln * 4]);

    // E warp tiling: 32 rows x 32 k ; M warp tiling: 32 k x 32 f
    int mgE = w >> 1, ngE = w & 1;
    int kgM = w >> 2, fgM = w & 3;

    // persistent M accumulators
    float macc[2][4][4];
    #pragma unroll
    for (int mt = 0; mt < 2; mt++)
        #pragma unroll
        for (int nt = 0; nt < 4; nt++)
            #pragma unroll
            for (int c = 0; c < 4; c++) macc[mt][nt][c] = 0.f;

    for (int tile = 0; tile < TPC; tile++) {
        int n0 = (part * TPC + tile) * TN;

        if (t < TN) rs[t] = 0.f;

        // ---- phase 1: load + normalize x; fill XH/XL (n-major), XTH/XTL (f-major); x2 ----
        const float4* ep = (const float4*)(emb + ((size_t)b * NN + n0) * FF);
        for (int j = 0; j < 16; j++) {
            int r = w + 8 * j;        // whole warp on one row
            float4 v = ep[(size_t)r * 32 + ln];
            float x0, x1, x2v, x3;
            if (n0 + r < nb) {
                x0 = (v.x - mean4.x) * inv4.x;
                x1 = (v.y - mean4.y) * inv4.y;
                x2v = (v.z - mean4.z) * inv4.z;
                x3 = (v.w - mean4.w) * inv4.w;
            } else {
                x0 = x1 = x2v = x3 = 0.f;
            }
            __nv_bfloat16 h0 = __float2bfloat16(x0);
            __nv_bfloat16 h1 = __float2bfloat16(x1);
            __nv_bfloat16 h2 = __float2bfloat16(x2v);
            __nv_bfloat16 h3 = __float2bfloat16(x3);
            __nv_bfloat16 l0 = __float2bfloat16(x0 - __bfloat162float(h0));
            __nv_bfloat16 l1 = __float2bfloat16(x1 - __bfloat162float(h1));
            __nv_bfloat16 l2 = __float2bfloat16(x2v - __bfloat162float(h2));
            __nv_bfloat16 l3 = __float2bfloat16(x3 - __bfloat162float(h3));
            *(uint32_t*)(sm + OFF_XH + r * PITCH + ln * 8)     = bpack(h0, h1);
            *(uint32_t*)(sm + OFF_XH + r * PITCH + ln * 8 + 4) = bpack(h2, h3);
            *(uint32_t*)(sm + OFF_XL + r * PITCH + ln * 8)     = bpack(l0, l1);
            *(uint32_t*)(sm + OFF_XL + r * PITCH + ln * 8 + 4) = bpack(l2, l3);
            int fb = ln * 4;
            *(__nv_bfloat16*)(sm + OFF_XTH + (fb + 0) * PITCH + r * 2) = h0;
            *(__nv_bfloat16*)(sm + OFF_XTH + (fb + 1) * PITCH + r * 2) = h1;
            *(__nv_bfloat16*)(sm + OFF_XTH + (fb + 2) * PITCH + r * 2) = h2;
            *(__nv_bfloat16*)(sm + OFF_XTH + (fb + 3) * PITCH + r * 2) = h3;
            *(__nv_bfloat16*)(sm + OFF_XTL + (fb + 0) * PITCH + r * 2) = l0;
            *(__nv_bfloat16*)(sm + OFF_XTL + (fb + 1) * PITCH + r * 2) = l1;
            *(__nv_bfloat16*)(sm + OFF_XTL + (fb + 2) * PITCH + r * 2) = l2;
            *(__nv_bfloat16*)(sm + OFF_XTL + (fb + 3) * PITCH + r * 2) = l3;
            float s = x0 * x0 + x1 * x1 + x2v * x2v + x3 * x3;
            s += __shfl_xor_sync(0xffffffffu, s, 16);
            s += __shfl_xor_sync(0xffffffffu, s, 8);
            s += __shfl_xor_sync(0xffffffffu, s, 4);
            s += __shfl_xor_sync(0xffffffffu, s, 2);
            s += __shfl_xor_sync(0xffffffffu, s, 1);
            if (ln == 0) x2s[r] = s;
        }
        __syncthreads();

        // ---- phase 2: E GEMM  S[n][k] = x . mu^T  (3 split terms) ----
        float eacc[2][4][4];
        #pragma unroll
        for (int mt = 0; mt < 2; mt++)
            #pragma unroll
            for (int nt = 0; nt < 4; nt++)
                #pragma unroll
                for (int c = 0; c < 4; c++) eacc[mt][nt][c] = 0.f;

        for (int kt = 0; kt < 8; kt++) {
            int f0 = kt * 16 + tg * 2;
            uint32_t ah[2][4], al[2][4], bh[4][2], bl[4][2];
            #pragma unroll
            for (int mt = 0; mt < 2; mt++) {
                int rb = mgE * 32 + mt * 16;
                ah[mt][0] = *(const uint32_t*)(sm + OFF_XH + (rb + g) * PITCH + f0 * 2);
                ah[mt][1] = *(const uint32_t*)(sm + OFF_XH + (rb + g + 8) * PITCH + f0 * 2);
                ah[mt][2] = *(const uint32_t*)(sm + OFF_XH + (rb + g) * PITCH + (f0 + 8) * 2);
                ah[mt][3] = *(const uint32_t*)(sm + OFF_XH + (rb + g + 8) * PITCH + (f0 + 8) * 2);
                al[mt][0] = *(const uint32_t*)(sm + OFF_XL + (rb + g) * PITCH + f0 * 2);
                al[mt][1] = *(const uint32_t*)(sm + OFF_XL + (rb + g + 8) * PITCH + f0 * 2);
                al[mt][2] = *(const uint32_t*)(sm + OFF_XL + (rb + g) * PITCH + (f0 + 8) * 2);
                al[mt][3] = *(const uint32_t*)(sm + OFF_XL + (rb + g + 8) * PITCH + (f0 + 8) * 2);
            }
            #pragma unroll
            for (int nt = 0; nt < 4; nt++) {
                int kc = ngE * 32 + nt * 8 + g;
                bh[nt][0] = *(const uint32_t*)(sm + OFF_MUH + kc * PITCH + f0 * 2);
                bh[nt][1] = *(const uint32_t*)(sm + OFF_MUH + kc * PITCH + (f0 + 8) * 2);
                bl[nt][0] = *(const uint32_t*)(sm + OFF_MUL + kc * PITCH + f0 * 2);
                bl[nt][1] = *(const uint32_t*)(sm + OFF_MUL + kc * PITCH + (f0 + 8) * 2);
            }
            #pragma unroll
            for (int mt = 0; mt < 2; mt++)
                #pragma unroll
                for (int nt = 0; nt < 4; nt++) {
                    mma16816(eacc[mt][nt], ah[mt], bh[nt]);
                    mma16816(eacc[mt][nt], al[mt], bh[nt]);
                    mma16816(eacc[mt][nt], ah[mt], bl[nt]);
                }
        }

        // ---- phase 3: likelihood + row sums ----
        #pragma unroll
        for (int mt = 0; mt < 2; mt++) {
            int r0 = mgE * 32 + mt * 16 + g;
            float xx0 = x2s[r0], xx1 = x2s[r0 + 8];
            float pr0 = 0.f, pr1 = 0.f;
            #pragma unroll
            for (int nt = 0; nt < 4; nt++) {
                int k0 = ngE * 32 + nt * 8 + tg * 2;
                float mm0 = m2s[k0], mm1 = m2s[k0 + 1];
                float l00 = fexp2(-0.72134752f * (xx0 - 2.f * eacc[mt][nt][0] + mm0)) + 1e-20f;
                float l01 = fexp2(-0.72134752f * (xx0 - 2.f * eacc[mt][nt][1] + mm1)) + 1e-20f;
                float l10 = fexp2(-0.72134752f * (xx1 - 2.f * eacc[mt][nt][2] + mm0)) + 1e-20f;
                float l11 = fexp2(-0.72134752f * (xx1 - 2.f * eacc[mt][nt][3] + mm1)) + 1e-20f;
                eacc[mt][nt][0] = l00; eacc[mt][nt][1] = l01;
                eacc[mt][nt][2] = l10; eacc[mt][nt][3] = l11;
                pr0 += l00 + l01;
                pr1 += l10 + l11;
            }
            pr0 += __shfl_xor_sync(0xffffffffu, pr0, 1);
            pr0 += __shfl_xor_sync(0xffffffffu, pr0, 2);
            pr1 += __shfl_xor_sync(0xffffffffu, pr1, 1);
            pr1 += __shfl_xor_sync(0xffffffffu, pr1, 2);
            if (tg == 0) {
                atomicAdd(&rs[r0], pr0);
                atomicAdd(&rs[r0 + 8], pr1);
            }
        }
        __syncthreads();

        // normalize and store P^T (bf16 hi/lo, k rows, n contiguous)
        #pragma unroll
        for (int mt = 0; mt < 2; mt++) {
            int r0 = mgE * 32 + mt * 16 + g;
            float i0 = 1.f / (rs[r0] + 1e-40f);
            float i1 = 1.f / (rs[r0 + 8] + 1e-40f);
            #pragma unroll
            for (int nt = 0; nt < 4; nt++) {
                int k0 = ngE * 32 + nt * 8 + tg * 2;
                float p00 = eacc[mt][nt][0] * i0;
                float p01 = eacc[mt][nt][1] * i0;
                float p10 = eacc[mt][nt][2] * i1;
                float p11 = eacc[mt][nt][3] * i1;
                __nv_bfloat16 h;
                h = __float2bfloat16(p00);
                *(__nv_bfloat16*)(sm + OFF_PTH + k0 * PITCH + r0 * 2) = h;
                *(__nv_bfloat16*)(sm + OFF_PTL + k0 * PITCH + r0 * 2) = __float2bfloat16(p00 - __bfloat162float(h));
                h = __float2bfloat16(p01);
                *(__nv_bfloat16*)(sm + OFF_PTH + (k0 + 1) * PITCH + r0 * 2) = h;
                *(__nv_bfloat16*)(sm + OFF_PTL + (k0 + 1) * PITCH + r0 * 2) = __float2bfloat16(p01 - __bfloat162float(h));
                h = __float2bfloat16(p10);
                *(__nv_bfloat16*)(sm + OFF_PTH + k0 * PITCH + (r0 + 8) * 2) = h;
                *(__nv_bfloat16*)(sm + OFF_PTL + k0 * PITCH + (r0 + 8) * 2) = __float2bfloat16(p10 - __bfloat162float(h));
                h = __float2bfloat16(p11);
                *(__nv_bfloat16*)(sm + OFF_PTH + (k0 + 1) * PITCH + (r0 + 8) * 2) = h;
                *(__nv_bfloat16*)(sm + OFF_PTL + (k0 + 1) * PITCH + (r0 + 8) * 2) = __float2bfloat16(p11 - __bfloat162float(h));
            }
        }
        __syncthreads();

        // ---- phase 4: M GEMM  MU[k][f] += P^T . x  (3 split terms) ----
        for (int kt = 0; kt < 8; kt++) {
            int nn0 = kt * 16 + tg * 2;
            uint32_t ah[2][4], al[2][4], bh[4][2], bl[4][2];
            #pragma unroll
            for (int mt = 0; mt < 2; mt++) {
                int rb = kgM * 32 + mt * 16;
                ah[mt][0] = *(const uint32_t*)(sm + OFF_PTH + (rb + g) * PITCH + nn0 * 2);
                ah[mt][1] = *(const uint32_t*)(sm + OFF_PTH + (rb + g + 8) * PITCH + nn0 * 2);
                ah[mt][2] = *(const uint32_t*)(sm + OFF_PTH + (rb + g) * PITCH + (nn0 + 8) * 2);
                ah[mt][3] = *(const uint32_t*)(sm + OFF_PTH + (rb + g + 8) * PITCH + (nn0 + 8) * 2);
                al[mt][0] = *(const uint32_t*)(sm + OFF_PTL + (rb + g) * PITCH + nn0 * 2);
                al[mt][1] = *(const uint32_t*)(sm + OFF_PTL + (rb + g + 8) * PITCH + nn0 * 2);
                al[mt][2] = *(const uint32_t*)(sm + OFF_PTL + (rb + g) * PITCH + (nn0 + 8) * 2);
                al[mt][3] = *(const uint32_t*)(sm + OFF_PTL + (rb + g + 8) * PITCH + (nn0 + 8) * 2);
            }
            #pragma unroll
            for (int nt = 0; nt < 4; nt++) {
                int fc = fgM * 32 + nt * 8 + g;
                bh[nt][0] = *(const uint32_t*)(sm + OFF_XTH + fc * PITCH + nn0 * 2);
                bh[nt][1] = *(const uint32_t*)(sm + OFF_XTH + fc * PITCH + (nn0 + 8) * 2);
                bl[nt][0] = *(const uint32_t*)(sm + OFF_XTL + fc * PITCH + nn0 * 2);
                bl[nt][1] = *(const uint32_t*)(sm + OFF_XTL + fc * PITCH + (nn0 + 8) * 2);
            }
            #pragma unroll
            for (int mt = 0; mt < 2; mt++)
                #pragma unroll
                for (int nt = 0; nt < 4; nt++) {
                    mma16816(macc[mt][nt], ah[mt], bh[nt]);
                    mma16816(macc[mt][nt], al[mt], bh[nt]);
                    mma16816(macc[mt][nt], ah[mt], bl[nt]);
                }
        }
        __syncthreads();   // xs/XT/PT/rs reused next tile
    }

    // ---- write partials [k][f] ----
    float* mp = g_part + ((size_t)(b * NPART + part)) * KK * FF;
    #pragma unroll
    for (int mt = 0; mt < 2; mt++)
        #pragma unroll
        for (int nt = 0; nt < 4; nt++) {
            int k0 = kgM * 32 + mt * 16 + g;
            int f0 = fgM * 32 + nt * 8 + tg * 2;
            mp[k0 * FF + f0]           = macc[mt][nt][0];
            mp[k0 * FF + f0 + 1]       = macc[mt][nt][1];
            mp[(k0 + 8) * FF + f0]     = macc[mt][nt][2];
            mp[(k0 + 8) * FF + f0 + 1] = macc[mt][nt][3];
        }
}

// ---------------------------------------------------------------------------
// Kernel 4: reduce partials -> mu out ([k][f]); grid BB*4 for parallelism
// ---------------------------------------------------------------------------
__global__ void __launch_bounds__(256)
reduce_mu_kernel(float* __restrict__ mu_out) {
    int b = blockIdx.x >> 2;
    int q = blockIdx.x & 3;
    const float4* p = (const float4*)(g_part + (size_t)b * NPART * KK * FF);
    float4* o = (float4*)(mu_out + (size_t)b * KK * FF);
    for (int i = threadIdx.x; i < 512; i += 256) {
        int idx = q * 512 + i;
        float4 a = make_float4(0.f, 0.f, 0.f, 0.f);
        #pragma unroll
        for (int pp = 0; pp < NPART; pp++) {
            float4 v = p[pp * (KK * FF / 4) + idx];
            a.x += v.x; a.y += v.y; a.z += v.z; a.w += v.w;
        }
        o[idx] = a;
    }
}

// ---------------------------------------------------------------------------
// Kernel 5: out[b] = sigmoid( mean_k(mu[b,k,:] . w) + bias )
// ---------------------------------------------------------------------------
__global__ void __launch_bounds__(128)
final_kernel(const float* __restrict__ mu, const float* __restrict__ w,
             const float* __restrict__ bias, float* __restrict__ out) {
    int b = blockIdx.x;
    int t = threadIdx.x;   // feature
    const float* m = mu + (size_t)b * KK * FF;
    float s = 0.f;
    for (int k = 0; k < KK; k++) s += m[k * FF + t];
    float v = s * w[t] * (1.f / (float)KK);
    __shared__ float sh[128];
    sh[t] = v;
    __syncthreads();
    for (int off = 64; off > 0; off >>= 1) {
        if (t < off) sh[t] += sh[t + off];
        __syncthreads();
    }
    if (t == 0) {
        float logit = sh[0] + bias[0];
        out[b] = 1.f / (1.f + expf(-logit));
    }
}

// ---------------------------------------------------------------------------
// Launch
// ---------------------------------------------------------------------------
extern "C" void kernel_launch(void* const* d_in, const int* in_sizes, int n_in,
                              void* d_out, int out_size) {
    const float* emb   = (const float*)d_in[0];
    const float* fc_w  = (const float*)d_in[2];
    const float* fc_b  = (const float*)d_in[3];
    const int*   nbn   = (const int*)d_in[4];
    const int*   iidx  = (const int*)d_in[5];
    float* out = (float*)d_out;

    (void)in_sizes; (void)n_in; (void)out_size;

    float* muA; cudaGetSymbolAddress((void**)&muA, g_muA);
    float* muB; cudaGetSymbolAddress((void**)&muB, g_muB);

    cudaFuncSetAttribute(em_kernel, cudaFuncAttributeMaxDynamicSharedMemorySize, SMEM_TOTAL);

    dim3 em_grid(NPART, BB);

    stats_kernel<<<BB, 512>>>(emb, nbn);                      // launch 1
    init_mu_kernel<<<BB, 256>>>(emb, nbn, iidx);              // launch 2

    em_kernel<<<em_grid, 256, SMEM_TOTAL>>>(emb, nbn, muA);   // launch 3 (step 1)
    reduce_mu_kernel<<<BB * 4, 256>>>(muB);                   // launch 4
    noop_kernel<<<1, 1>>>();                                  // launch 5 (ncu -s 5 alignment)
    em_kernel<<<em_grid, 256, SMEM_TOTAL>>>(emb, nbn, muB);   // launch 6 (step 2) <- profiled
    reduce_mu_kernel<<<BB * 4, 256>>>(muA);
    em_kernel<<<em_grid, 256, SMEM_TOTAL>>>(emb, nbn, muA);   // step 3
    reduce_mu_kernel<<<BB * 4, 256>>>(muB);
    em_kernel<<<em_grid, 256, SMEM_TOTAL>>>(emb, nbn, muB);   // step 4
    reduce_mu_kernel<<<BB * 4, 256>>>(muA);

    final_kernel<<<BB, 128>>>(muA, fc_w, fc_b, out);
}